// round 16
// baseline (speedup 1.0000x reference)
#include <cuda_runtime.h>
#include <cuda_bf16.h>
#include <math.h>
#include <stdint.h>

// Problem constants
#define BQ 4
#define HH 64
#define WW 64
#define CC 128
#define DI 256
#define NS 16
#define RR 8
#define LL 4096       // H*W
#define BL (BQ*LL)    // 16384 pixel-rows
#define CS 128        // scan chunk size
#define NCH (LL/CS)   // 32 chunks

// -------------------- device scratch (static, no allocs) --------------------
__device__ __align__(16) float g_xd[BL*160];       // x_proj output fp32
__device__ __align__(16) float g_y [BL*DI];        // scan merged output
__device__ __align__(16) float g_xmid[BL*CC];      // after out_proj + residual
__device__ __align__(16) float g_P[16*NCH*NS*DI];
__device__ __align__(16) float g_S[16*NCH*NS*DI];
// bf16 activations
__device__ __align__(16) __nv_bfloat16 g_x1b [BL*DI];   // x_ (conv input)
__device__ __align__(16) __nv_bfloat16 g_szb [BL*DI];   // silu(z)
__device__ __align__(16) __nv_bfloat16 g_xn1b[BL*CC];   // LN1(input)
__device__ __align__(16) __nv_bfloat16 g_xcb [BL*DI];   // conv out (GEMM A + scan xt)
__device__ __align__(16) __nv_bfloat16 g_ynb [BL*DI];   // onorm*silu(z)
__device__ __align__(16) __nv_bfloat16 g_xn2b[BL*CC];   // LN2(xmid)
__device__ __align__(16) __nv_bfloat16 g_hb  [BL*4*CC]; // MLP hidden
// bf16 weights, transposed to [N][K]
__device__ __align__(16) __nv_bfloat16 wb_in[512*128];
__device__ __align__(16) __nv_bfloat16 wb_xp[256*256];
__device__ __align__(16) __nv_bfloat16 wb_op[128*256];
__device__ __align__(16) __nv_bfloat16 wb_f1[512*128];
__device__ __align__(16) __nv_bfloat16 wb_f2[128*512];

// -------------------- small math helpers --------------------
__device__ __forceinline__ float silu_f(float x){ return x / (1.f + __expf(-x)); }
__device__ __forceinline__ float softplus_f(float x){
    return fmaxf(x, 0.f) + __logf(1.f + __expf(-fabsf(x)));
}
__device__ __forceinline__ float gelu_f(float x){
    return 0.5f * x * (1.f + erff(x * 0.70710678118654752f));
}
__device__ __forceinline__ void mma_bf16(float c[4], const uint32_t a[4], const uint32_t b[2]){
    asm volatile(
        "mma.sync.aligned.m16n8k16.row.col.f32.bf16.bf16.f32 "
        "{%0,%1,%2,%3},{%4,%5,%6,%7},{%8,%9},{%0,%1,%2,%3};"
        : "+f"(c[0]), "+f"(c[1]), "+f"(c[2]), "+f"(c[3])
        : "r"(a[0]), "r"(a[1]), "r"(a[2]), "r"(a[3]), "r"(b[0]), "r"(b[1]));
}
__device__ __forceinline__ void cp16(uint32_t dst, const void* src){
    asm volatile("cp.async.cg.shared.global [%0], [%1], 16;" :: "r"(dst), "l"(src));
}
// packed f32x2
__device__ __forceinline__ uint64_t pk2(float lo, float hi){
    uint64_t r; asm("mov.b64 %0, {%1,%2};" : "=l"(r) : "f"(lo), "f"(hi)); return r;
}
__device__ __forceinline__ void upk2(float& lo, float& hi, uint64_t v){
    asm("mov.b64 {%0,%1}, %2;" : "=f"(lo), "=f"(hi) : "l"(v));
}
__device__ __forceinline__ uint64_t mul2(uint64_t a, uint64_t b){
    uint64_t r; asm("mul.rn.f32x2 %0,%1,%2;" : "=l"(r) : "l"(a), "l"(b)); return r;
}
__device__ __forceinline__ uint64_t fma2(uint64_t a, uint64_t b, uint64_t c){
    uint64_t r; asm("fma.rn.f32x2 %0,%1,%2,%3;" : "=l"(r) : "l"(a), "l"(b), "l"(c)); return r;
}
__device__ __forceinline__ int pmap(int k, int T){
    int t = (k & 2) ? (LL - 1 - T) : T;
    return (k & 1) ? ((t & 63) * 64 + (t >> 6)) : t;
}

// -------------------- prep: bf16-convert + transpose all weights --------------------
__global__ void prep(const float* __restrict__ w_in, const float* __restrict__ w_xp,
                     const float* __restrict__ w_op, const float* __restrict__ w_f1,
                     const float* __restrict__ w_f2){
    int idx = blockIdx.x * 256 + threadIdx.x;
    if (idx < 65536){
        int n = idx >> 7, k2 = idx & 127;
        wb_in[idx] = __float2bfloat16(w_in[k2 * 512 + n]);
    } else if (idx < 131072){
        int j = idx - 65536; int n = j >> 8, k2 = j & 255;
        wb_xp[j] = __float2bfloat16((n < 160) ? w_xp[n * 256 + k2] : 0.f);
    } else if (idx < 163840){
        int j = idx - 131072; int n = j >> 8, k2 = j & 255;
        wb_op[j] = __float2bfloat16(w_op[k2 * 128 + n]);
    } else if (idx < 229376){
        int j = idx - 163840; int n = j >> 7, k2 = j & 127;
        wb_f1[j] = __float2bfloat16(w_f1[k2 * 512 + n]);
    } else if (idx < 294912){
        int j = idx - 229376; int n = j >> 9, k2 = j & 511;
        wb_f2[j] = __float2bfloat16(w_f2[k2 * 128 + n]);
    }
}

// -------------------- LN1 (writes bf16 rows) --------------------
__global__ void ln_norm(const float* __restrict__ x, __nv_bfloat16* __restrict__ xo,
                        const float* __restrict__ w, const float* __restrict__ b){
    int row = blockIdx.x;
    float v = x[(size_t)row * CC + threadIdx.x];
    float s1 = v, s2 = v * v;
    #pragma unroll
    for (int o = 16; o; o >>= 1){
        s1 += __shfl_xor_sync(0xffffffffu, s1, o);
        s2 += __shfl_xor_sync(0xffffffffu, s2, o);
    }
    __shared__ float r1[4], r2[4];
    int wi = threadIdx.x >> 5;
    if ((threadIdx.x & 31) == 0){ r1[wi] = s1; r2[wi] = s2; }
    __syncthreads();
    float a = 0.f, bb = 0.f;
    #pragma unroll
    for (int i = 0; i < 4; i++){ a += r1[i]; bb += r2[i]; }
    float mu = a / CC;
    float var = bb / CC - mu * mu;
    float rs = rsqrtf(var + 1e-5f);
    xo[(size_t)row * CC + threadIdx.x] =
        __float2bfloat16((v - mu) * rs * w[threadIdx.x] + b[threadIdx.x]);
}

// -------------------- BF16 tensor-core GEMM, cp.async 3-stage --------------------
#define STG_W 5120
#define A_STGB (128*80)
#define STGB (2*A_STGB)
#define GEMM_SMEM 67584

// EPI: 0 plain(+Nguard) | 1 dual-split bf16 (outb2 = x_, outb = silu(z))
//      2 bias+gelu->bf16 | 3 bias?+residual->fp32 | 4 residual + fused LN
template<int EPI>
__global__ void __launch_bounds__(256, 2) gemm_bf(
    const __nv_bfloat16* __restrict__ A, const __nv_bfloat16* __restrict__ Bw,
    float* __restrict__ Cmat, int M, int Nn, int Kk,
    const float* __restrict__ bias, const float* __restrict__ res,
    __nv_bfloat16* __restrict__ outb, __nv_bfloat16* __restrict__ outb2,
    const float* __restrict__ lnw, const float* __restrict__ lnb)
{
    extern __shared__ float smem[];
    uint32_t sbase;
    { void* p = smem; sbase = (uint32_t)__cvta_generic_to_shared(p); }
    uint32_t* Ss = reinterpret_cast<uint32_t*>(smem);

    const int tid = threadIdx.x;
    const int lane = tid & 31, wid = tid >> 5;
    const int wm = wid & 3, wn = wid >> 2;
    const int t = lane & 3, g = lane >> 2;
    const int bm = blockIdx.y * 128;
    const int bn = blockIdx.x * 128;
    const int lrow = tid >> 2, lc = tid & 3;

    float acc[2][8][4];
    #pragma unroll
    for (int i = 0; i < 2; i++)
        #pragma unroll
        for (int j = 0; j < 8; j++)
            #pragma unroll
            for (int e = 0; e < 4; e++) acc[i][j][e] = 0.f;

    const int nk = Kk >> 5;

    auto load_stage = [&](int stage, int kt){
        uint32_t abase = sbase + stage * STGB;
        #pragma unroll
        for (int q = 0; q < 2; q++){
            int row = q * 64 + lrow;
            cp16(abase + row * 80 + lc * 16,
                 &A[(size_t)(bm + row) * Kk + kt + lc * 8]);
        }
        uint32_t bbase = abase + A_STGB;
        #pragma unroll
        for (int q = 0; q < 2; q++){
            int row = q * 64 + lrow;
            cp16(bbase + row * 80 + lc * 16,
                 &Bw[(size_t)(bn + row) * Kk + kt + lc * 8]);
        }
    };

    load_stage(0, 0);
    asm volatile("cp.async.commit_group;");
    if (nk > 1) load_stage(1, 32);
    asm volatile("cp.async.commit_group;");

    int st = 0;
    for (int i = 0; i < nk; i++){
        asm volatile("cp.async.wait_group 1;");
        __syncthreads();

        const uint32_t* Ab = Ss + st * STG_W;
        const uint32_t* Bb = Ab + 2560;
        if (i + 2 < nk){
            int s2 = st + 2; if (s2 >= 3) s2 -= 3;
            load_stage(s2, (i + 2) << 5);
        }
        asm volatile("cp.async.commit_group;");

        #pragma unroll
        for (int ks = 0; ks < 2; ks++){
            int kw = ks * 8 + t;
            uint32_t afr[2][4];
            #pragma unroll
            for (int mt = 0; mt < 2; mt++){
                int mr = wm * 32 + mt * 16 + g;
                afr[mt][0] = Ab[mr * 20 + kw];
                afr[mt][1] = Ab[(mr + 8) * 20 + kw];
                afr[mt][2] = Ab[mr * 20 + kw + 4];
                afr[mt][3] = Ab[(mr + 8) * 20 + kw + 4];
            }
            uint32_t bfr[8][2];
            #pragma unroll
            for (int nt = 0; nt < 8; nt++){
                int nc = wn * 64 + nt * 8 + g;
                bfr[nt][0] = Bb[nc * 20 + kw];
                bfr[nt][1] = Bb[nc * 20 + kw + 4];
            }
            #pragma unroll
            for (int mt = 0; mt < 2; mt++)
                #pragma unroll
                for (int nt = 0; nt < 8; nt++)
                    mma_bf16(acc[mt][nt], afr[mt], bfr[nt]);
        }
        if (++st == 3) st = 0;
    }

    if (EPI == 4){
        __syncthreads();
        float* sred = smem;   // stride 132
        #pragma unroll
        for (int mt = 0; mt < 2; mt++){
            #pragma unroll
            for (int nt = 0; nt < 8; nt++){
                int cl = wn * 64 + nt * 8 + 2 * t;
                #pragma unroll
                for (int h = 0; h < 2; h++){
                    int rl = wm * 32 + mt * 16 + g + h * 8;
                    float2 rv = *reinterpret_cast<const float2*>(
                        &res[(size_t)(bm + rl) * 128 + cl]);
                    sred[rl * 132 + cl]     = acc[mt][nt][h * 2 + 0] + rv.x;
                    sred[rl * 132 + cl + 1] = acc[mt][nt][h * 2 + 1] + rv.y;
                }
            }
        }
        __syncthreads();
        float4 wv = *reinterpret_cast<const float4*>(&lnw[lane * 4]);
        float4 bv = *reinterpret_cast<const float4*>(&lnb[lane * 4]);
        #pragma unroll
        for (int rr = 0; rr < 16; rr++){
            int rl = wid * 16 + rr;
            float4 v = *reinterpret_cast<const float4*>(&sred[rl * 132 + lane * 4]);
            float s1 = v.x + v.y + v.z + v.w;
            float s2 = fmaf(v.x, v.x, fmaf(v.y, v.y, fmaf(v.z, v.z, v.w * v.w)));
            #pragma unroll
            for (int o = 16; o; o >>= 1){
                s1 += __shfl_xor_sync(0xffffffffu, s1, o);
                s2 += __shfl_xor_sync(0xffffffffu, s2, o);
            }
            float mu = s1 * (1.f / 128.f);
            float var = s2 * (1.f / 128.f) - mu * mu;
            float rs = rsqrtf(var + 1e-5f);
            size_t go = (size_t)(bm + rl) * 128 + lane * 4;
            *reinterpret_cast<float4*>(&Cmat[go]) = v;
            __nv_bfloat162* ob = reinterpret_cast<__nv_bfloat162*>(&outb[go]);
            ob[0] = __floats2bfloat162_rn((v.x - mu) * rs * wv.x + bv.x,
                                          (v.y - mu) * rs * wv.y + bv.y);
            ob[1] = __floats2bfloat162_rn((v.z - mu) * rs * wv.z + bv.z,
                                          (v.w - mu) * rs * wv.w + bv.w);
        }
        return;
    }

    #pragma unroll
    for (int mt = 0; mt < 2; mt++){
        #pragma unroll
        for (int nt = 0; nt < 8; nt++){
            int r0 = bm + wm * 32 + mt * 16 + g;
            int c0 = bn + wn * 64 + nt * 8 + 2 * t;
            #pragma unroll
            for (int h = 0; h < 2; h++){
                int r = r0 + h * 8;
                float v0 = acc[mt][nt][h * 2 + 0];
                float v1 = acc[mt][nt][h * 2 + 1];
                if (EPI == 1){
                    if (c0 < 256)
                        *reinterpret_cast<__nv_bfloat162*>(
                            &outb2[(size_t)r * 256 + c0]) =
                            __floats2bfloat162_rn(v0, v1);
                    else
                        *reinterpret_cast<__nv_bfloat162*>(
                            &outb[(size_t)r * 256 + (c0 - 256)]) =
                            __floats2bfloat162_rn(silu_f(v0), silu_f(v1));
                } else if (EPI == 2){
                    v0 = gelu_f(v0 + bias[c0]);
                    v1 = gelu_f(v1 + bias[c0 + 1]);
                    *reinterpret_cast<__nv_bfloat162*>(&outb[(size_t)r * Nn + c0]) =
                        __floats2bfloat162_rn(v0, v1);
                } else if (EPI == 3){
                    if (bias){ v0 += bias[c0]; v1 += bias[c0 + 1]; }
                    float2 rv = *reinterpret_cast<const float2*>(&res[(size_t)r * Nn + c0]);
                    *reinterpret_cast<float2*>(&Cmat[(size_t)r * Nn + c0]) =
                        make_float2(v0 + rv.x, v1 + rv.y);
                } else {
                    if (c0 < Nn)
                        *reinterpret_cast<float2*>(&Cmat[(size_t)r * Nn + c0]) =
                            make_float2(v0, v1);
                }
            }
        }
    }
}

// -------------------- depthwise 3x3 conv (bf16 in, bf16 out) --------------------
#define CPG 32
#define CONV_SMEM (3*66*CPG*4)
__global__ void __launch_bounds__(256) conv_dw(const float* __restrict__ wc,
                                               const float* __restrict__ bc){
    extern __shared__ float cs[];   // [3][66][CPG]
    const int c0 = blockIdx.x * CPG;
    const int h  = blockIdx.y;
    const int b  = blockIdx.z;
    const int tid = threadIdx.x;

    if (tid < 48){
        int r = tid / 16;
        int col = (tid >> 3) & 1;
        int c4 = tid & 7;
        *reinterpret_cast<float4*>(&cs[(r * 66 + col * 65) * CPG + c4 * 4]) =
            make_float4(0.f, 0.f, 0.f, 0.f);
    }
    #pragma unroll
    for (int r = 0; r < 3; r++){
        int hh = h + r - 1;
        if (hh >= 0 && hh < HH){
            const __nv_bfloat16* src = &g_x1b[((size_t)(b * LL + hh * WW)) * DI + c0];
            #pragma unroll
            for (int q = 0; q < 2; q++){
                int idx = q * 256 + tid;
                int w = idx >> 3, c4 = idx & 7;
                const __nv_bfloat162* sp = reinterpret_cast<const __nv_bfloat162*>(
                    &src[(size_t)w * DI + c4 * 4]);
                float2 lo = __bfloat1622float2(sp[0]);
                float2 hi = __bfloat1622float2(sp[1]);
                *reinterpret_cast<float4*>(&cs[(r * 66 + w + 1) * CPG + c4 * 4]) =
                    make_float4(lo.x, lo.y, hi.x, hi.y);
            }
        } else {
            #pragma unroll
            for (int q = 0; q < 2; q++){
                int idx = q * 256 + tid;
                int w = idx >> 3, c4 = idx & 7;
                *reinterpret_cast<float4*>(&cs[(r * 66 + w + 1) * CPG + c4 * 4]) =
                    make_float4(0.f, 0.f, 0.f, 0.f);
            }
        }
    }
    __syncthreads();

    const int cg = tid & 15;
    const int wt = tid >> 4;
    const int d = c0 + cg * 2;
    const int w0 = wt * 4;

    float wr[2][9];
    #pragma unroll
    for (int e = 0; e < 2; e++)
        #pragma unroll
        for (int j = 0; j < 9; j++) wr[e][j] = wc[(d + e) * 9 + j];
    const float2 bias = *reinterpret_cast<const float2*>(&bc[d]);

    float2 acc[4];
    #pragma unroll
    for (int o = 0; o < 4; o++) acc[o] = bias;

    #pragma unroll
    for (int r = 0; r < 3; r++){
        #pragma unroll
        for (int j = 0; j < 6; j++){
            float2 v = *reinterpret_cast<const float2*>(
                &cs[(r * 66 + w0 + j) * CPG + cg * 2]);
            #pragma unroll
            for (int o = 0; o < 4; o++){
                if (o <= j && j <= o + 2){
                    int tap = r * 3 + (j - o);
                    acc[o].x = fmaf(wr[0][tap], v.x, acc[o].x);
                    acc[o].y = fmaf(wr[1][tap], v.y, acc[o].y);
                }
            }
        }
    }
    #pragma unroll
    for (int o = 0; o < 4; o++){
        size_t gi = ((size_t)(b * LL + h * WW + w0 + o)) * DI + d;
        *reinterpret_cast<__nv_bfloat162*>(&g_xcb[gi]) =
            __floats2bfloat162_rn(silu_f(acc[o].x), silu_f(acc[o].y));
    }
}

// -------------------- selective scan: pass 1 (chunk-local, dts+B only) --------------------
__global__ void __launch_bounds__(256) scan_pass1(
    const float* __restrict__ dtw, const float* __restrict__ dtb,
    const float* __restrict__ alog)
{
    int bk = blockIdx.x;
    int chunk = blockIdx.y;
    int b = bk >> 2, k = bk & 3;
    int d = threadIdx.x;
    __shared__ __align__(16) float tile[CS * 24];   // dts(8) + B(16)
    int T0 = chunk * CS;
    {
        float4* tile4 = reinterpret_cast<float4*>(tile);
        const float4* xd4 = reinterpret_cast<const float4*>(g_xd);
        for (int i = d; i < CS * 6; i += 256){
            int t = i / 6, c = i - t * 6;
            int p = pmap(k, T0 + t);
            tile4[t * 6 + c] = xd4[(size_t)(b * LL + p) * 40 + k * 10 + c];
        }
    }
    __syncthreads();

    float dw[RR];
    #pragma unroll
    for (int r = 0; r < RR; r++) dw[r] = dtw[(size_t)(k * DI + d) * RR + r];
    float db = dtb[k * DI + d];
    float Av[NS];
    #pragma unroll
    for (int n = 0; n < NS; n++) Av[n] = -__expf(alog[(size_t)(k * DI + d) * NS + n]);
    float A0 = Av[0];
    bool fast = true;
    #pragma unroll
    for (int n = 0; n < NS; n++){
        float e = Av[n] - (float)(n + 1) * A0;
        if (fabsf(e) > 1e-5f * fabsf(Av[n]) + 1e-12f) fast = false;
    }
    float dsum = 0.f;
    size_t base = ((size_t)(bk * NCH + chunk) * NS) * DI + d;

    if (fast){
        uint64_t hv[8];
        #pragma unroll
        for (int i = 0; i < 8; i++) hv[i] = pk2(0.f, 0.f);
        for (int t = 0; t < CS; t++){
            int p = pmap(k, T0 + t);
            float xt = __bfloat162float(g_xcb[(size_t)(b * LL + p) * DI + d]);
            const float* tr = &tile[t * 24];
            float4 q0 = *reinterpret_cast<const float4*>(&tr[0]);
            float4 q1 = *reinterpret_cast<const float4*>(&tr[4]);
            float dp = db;
            dp = fmaf(dw[0], q0.x, dp); dp = fmaf(dw[1], q0.y, dp);
            dp = fmaf(dw[2], q0.z, dp); dp = fmaf(dw[3], q0.w, dp);
            dp = fmaf(dw[4], q1.x, dp); dp = fmaf(dw[5], q1.y, dp);
            dp = fmaf(dw[6], q1.z, dp); dp = fmaf(dw[7], q1.w, dp);
            float delta = softplus_f(dp);
            dsum += delta;
            float du = delta * xt;
            float gg = __expf(delta * A0);
            float g2 = gg * gg;
            uint64_t g2v = pk2(g2, g2);
            uint64_t a = pk2(gg, g2);
            uint64_t duv = pk2(du, du);
            #pragma unroll
            for (int j = 0; j < 4; j++){
                ulonglong2 B2 = *reinterpret_cast<const ulonglong2*>(&tr[8 + 4 * j]);
                hv[2*j]   = fma2(a, hv[2*j],   mul2(duv, B2.x));
                a = mul2(a, g2v);
                hv[2*j+1] = fma2(a, hv[2*j+1], mul2(duv, B2.y));
                if (j < 3) a = mul2(a, g2v);
            }
        }
        #pragma unroll
        for (int i = 0; i < 8; i++){
            float lo, hi;
            upk2(lo, hi, hv[i]);
            g_S[base + (size_t)(2 * i) * DI] = lo;
            g_S[base + (size_t)(2 * i + 1) * DI] = hi;
        }
    } else {
        float S[NS];
        #pragma unroll
        for (int n = 0; n < NS; n++) S[n] = 0.f;
        for (int t = 0; t < CS; t++){
            int p = pmap(k, T0 + t);
            float xt = __bfloat162float(g_xcb[(size_t)(b * LL + p) * DI + d]);
            const float* tr = &tile[t * 24];
            float dp = db;
            #pragma unroll
            for (int r = 0; r < RR; r++) dp = fmaf(dw[r], tr[r], dp);
            float delta = softplus_f(dp);
            dsum += delta;
            float du = delta * xt;
            #pragma unroll
            for (int n = 0; n < NS; n++){
                float a = __expf(delta * Av[n]);
                S[n] = fmaf(a, S[n], du * tr[8 + n]);
            }
        }
        #pragma unroll
        for (int n = 0; n < NS; n++) g_S[base + (size_t)n * DI] = S[n];
    }
    #pragma unroll
    for (int n = 0; n < NS; n++)
        g_P[base + (size_t)n * DI] = __expf(dsum * Av[n]);
}

// -------------------- scan pass 2: carry across chunks (+ zero g_y) --------------------
__global__ void scan_pass2(){
    int id = blockIdx.x * 256 + threadIdx.x;
    float4* y4 = reinterpret_cast<float4*>(g_y);
    #pragma unroll
    for (int q = 0; q < 16; q++)
        y4[(size_t)q * 65536 + id] = make_float4(0.f, 0.f, 0.f, 0.f);

    int d  = id & 255;
    int n  = (id >> 8) & 15;
    int bk = id >> 12;
    size_t stride = (size_t)NS * DI;
    size_t base = ((size_t)bk * NCH * NS + n) * DI + d;

    float Pv[NCH], Sv[NCH];
    #pragma unroll
    for (int c = 0; c < NCH; c++){
        Pv[c] = g_P[base + (size_t)c * stride];
        Sv[c] = g_S[base + (size_t)c * stride];
    }
    float Hc = 0.f;
    #pragma unroll
    for (int c = 0; c < NCH; c++){
        g_S[base + (size_t)c * stride] = Hc;
        Hc = fmaf(Pv[c], Hc, Sv[c]);
    }
}

// -------------------- scan pass 3: replay + y + merge (atomic) --------------------
__global__ void __launch_bounds__(256) scan_pass3(
    const float* __restrict__ dtw, const float* __restrict__ dtb,
    const float* __restrict__ alog, const float* __restrict__ Dsv)
{
    int bk = blockIdx.x;
    int chunk = blockIdx.y;
    int b = bk >> 2, k = bk & 3;
    int d = threadIdx.x;
    __shared__ __align__(16) float tile[CS * 40];
    int T0 = chunk * CS;
    {
        float4* tile4 = reinterpret_cast<float4*>(tile);
        const float4* xd4 = reinterpret_cast<const float4*>(g_xd);
        for (int i = d; i < CS * 10; i += 256){
            int t = i / 10, c = i - t * 10;
            int p = pmap(k, T0 + t);
            tile4[t * 10 + c] = xd4[(size_t)(b * LL + p) * 40 + k * 10 + c];
        }
    }
    __syncthreads();

    float dw[RR];
    #pragma unroll
    for (int r = 0; r < RR; r++) dw[r] = dtw[(size_t)(k * DI + d) * RR + r];
    float db = dtb[k * DI + d];
    float Dk = Dsv[k * DI + d];
    float Av[NS];
    #pragma unroll
    for (int n = 0; n < NS; n++) Av[n] = -__expf(alog[(size_t)(k * DI + d) * NS + n]);
    float A0 = Av[0];
    bool fast = true;
    #pragma unroll
    for (int n = 0; n < NS; n++){
        float e = Av[n] - (float)(n + 1) * A0;
        if (fabsf(e) > 1e-5f * fabsf(Av[n]) + 1e-12f) fast = false;
    }
    size_t base = ((size_t)(bk * NCH + chunk) * NS) * DI + d;

    if (fast){
        uint64_t hv[8];
        #pragma unroll
        for (int i = 0; i < 8; i++)
            hv[i] = pk2(g_S[base + (size_t)(2 * i) * DI],
                        g_S[base + (size_t)(2 * i + 1) * DI]);
        for (int t = 0; t < CS; t++){
            int p = pmap(k, T0 + t);
            size_t pidx = (size_t)(b * LL + p) * DI + d;
            float xt = __bfloat162float(g_xcb[pidx]);
            const float* tr = &tile[t * 40];
            float4 q0 = *reinterpret_cast<const float4*>(&tr[0]);
            float4 q1 = *reinterpret_cast<const float4*>(&tr[4]);
            float dp = db;
            dp = fmaf(dw[0], q0.x, dp); dp = fmaf(dw[1], q0.y, dp);
            dp = fmaf(dw[2], q0.z, dp); dp = fmaf(dw[3], q0.w, dp);
            dp = fmaf(dw[4], q1.x, dp); dp = fmaf(dw[5], q1.y, dp);
            dp = fmaf(dw[6], q1.z, dp); dp = fmaf(dw[7], q1.w, dp);
            float delta = softplus_f(dp);
            float du = delta * xt;
            float gg = __expf(delta * A0);
            float g2 = gg * gg;
            uint64_t g2v = pk2(g2, g2);
            uint64_t a = pk2(gg, g2);
            uint64_t duv = pk2(du, du);
            uint64_t yv = pk2(0.f, 0.f);
            #pragma unroll
            for (int j = 0; j < 4; j++){
                ulonglong2 B2 = *reinterpret_cast<const ulonglong2*>(&tr[8 + 4 * j]);
                ulonglong2 C2 = *reinterpret_cast<const ulonglong2*>(&tr[24 + 4 * j]);
                hv[2*j] = fma2(a, hv[2*j], mul2(duv, B2.x));
                yv = fma2(hv[2*j], C2.x, yv);
                a = mul2(a, g2v);
                hv[2*j+1] = fma2(a, hv[2*j+1], mul2(duv, B2.y));
                yv = fma2(hv[2*j+1], C2.y, yv);
                if (j < 3) a = mul2(a, g2v);
            }
            float ylo, yhi;
            upk2(ylo, yhi, yv);
            float y = ylo + yhi;
            y = fmaf(Dk, xt, y);
            atomicAdd(&g_y[pidx], y);
        }
    } else {
        float h[NS];
        #pragma unroll
        for (int n = 0; n < NS; n++) h[n] = g_S[base + (size_t)n * DI];
        for (int t = 0; t < CS; t++){
            int p = pmap(k, T0 + t);
            size_t pidx = (size_t)(b * LL + p) * DI + d;
            float xt = __bfloat162float(g_xcb[pidx]);
            const float* tr = &tile[t * 40];
            float dp = db;
            #pragma unroll
            for (int r = 0; r < RR; r++) dp = fmaf(dw[r], tr[r], dp);
            float delta = softplus_f(dp);
            float du = delta * xt;
            float y = 0.f;
            #pragma unroll
            for (int n = 0; n < NS; n++){
                float a = __expf(delta * Av[n]);
                h[n] = fmaf(a, h[n], du * tr[8 + n]);
                y = fmaf(h[n], tr[24 + n], y);
            }
            y = fmaf(Dk, xt, y);
            atomicAdd(&g_y[pidx], y);
        }
    }
}

// -------------------- out-norm (LN over DI) * silu(z) -> bf16 --------------------
__global__ void onorm_mul(const float* __restrict__ onw, const float* __restrict__ onb){
    int row = blockIdx.x;
    int d = threadIdx.x;
    float v = g_y[(size_t)row * DI + d];
    float s1 = v, s2 = v * v;
    #pragma unroll
    for (int o = 16; o; o >>= 1){
        s1 += __shfl_xor_sync(0xffffffffu, s1, o);
        s2 += __shfl_xor_sync(0xffffffffu, s2, o);
    }
    __shared__ float r1[8], r2[8];
    int w = d >> 5;
    if ((d & 31) == 0){ r1[w] = s1; r2[w] = s2; }
    __syncthreads();
    float a = 0.f, bsum = 0.f;
    #pragma unroll
    for (int i = 0; i < 8; i++){ a += r1[i]; bsum += r2[i]; }
    float mu = a / DI;
    float var = bsum / DI - mu * mu;
    float rs = rsqrtf(var + 1e-5f);
    float o = (v - mu) * rs * onw[d] + onb[d];
    float sz = __bfloat162float(g_szb[(size_t)row * DI + d]);
    g_ynb[(size_t)row * DI + d] = __float2bfloat16(o * sz);
}

// -------------------- host launch --------------------
extern "C" void kernel_launch(void* const* d_in, const int* in_sizes, int n_in,
                              void* d_out, int out_size)
{
    (void)in_sizes; (void)n_in; (void)out_size;
    const float* input     = (const float*)d_in[0];
    const float* ln1_w     = (const float*)d_in[1];
    const float* ln1_b     = (const float*)d_in[2];
    const float* in_proj_w = (const float*)d_in[3];
    const float* conv_w    = (const float*)d_in[4];
    const float* conv_b    = (const float*)d_in[5];
    const float* x_proj_w  = (const float*)d_in[6];
    const float* dt_w      = (const float*)d_in[7];
    const float* dt_b      = (const float*)d_in[8];
    const float* A_log     = (const float*)d_in[9];
    const float* Ds        = (const float*)d_in[10];
    const float* onorm_w   = (const float*)d_in[11];
    const float* onorm_b   = (const float*)d_in[12];
    const float* out_proj_w= (const float*)d_in[13];
    const float* ln2_w     = (const float*)d_in[14];
    const float* ln2_b     = (const float*)d_in[15];
    const float* fc1_w     = (const float*)d_in[16];
    const float* fc1_b     = (const float*)d_in[17];
    const float* fc2_w     = (const float*)d_in[18];
    const float* fc2_b     = (const float*)d_in[19];

    float *pxd, *pxmid;
    __nv_bfloat16 *px1b, *pszb, *pxn1b, *pxcb, *pynb, *pxn2b, *phb;
    __nv_bfloat16 *pwin, *pwxp, *pwop, *pwf1, *pwf2;
    cudaGetSymbolAddress((void**)&pxd,  g_xd);
    cudaGetSymbolAddress((void**)&pxmid,g_xmid);
    cudaGetSymbolAddress((void**)&px1b, g_x1b);
    cudaGetSymbolAddress((void**)&pszb, g_szb);
    cudaGetSymbolAddress((void**)&pxn1b,g_xn1b);
    cudaGetSymbolAddress((void**)&pxcb, g_xcb);
    cudaGetSymbolAddress((void**)&pynb, g_ynb);
    cudaGetSymbolAddress((void**)&pxn2b,g_xn2b);
    cudaGetSymbolAddress((void**)&phb,  g_hb);
    cudaGetSymbolAddress((void**)&pwin, wb_in);
    cudaGetSymbolAddress((void**)&pwxp, wb_xp);
    cudaGetSymbolAddress((void**)&pwop, wb_op);
    cudaGetSymbolAddress((void**)&pwf1, wb_f1);
    cudaGetSymbolAddress((void**)&pwf2, wb_f2);

    static bool attr_done = false;
    if (!attr_done){
        cudaFuncSetAttribute(gemm_bf<0>, cudaFuncAttributeMaxDynamicSharedMemorySize, GEMM_SMEM);
        cudaFuncSetAttribute(gemm_bf<1>, cudaFuncAttributeMaxDynamicSharedMemorySize, GEMM_SMEM);
        cudaFuncSetAttribute(gemm_bf<2>, cudaFuncAttributeMaxDynamicSharedMemorySize, GEMM_SMEM);
        cudaFuncSetAttribute(gemm_bf<3>, cudaFuncAttributeMaxDynamicSharedMemorySize, GEMM_SMEM);
        cudaFuncSetAttribute(gemm_bf<4>, cudaFuncAttributeMaxDynamicSharedMemorySize, GEMM_SMEM);
        cudaFuncSetAttribute(conv_dw,   cudaFuncAttributeMaxDynamicSharedMemorySize, CONV_SMEM);
        attr_done = true;
    }

    // 0. weight conversion (bf16 + transpose)
    prep<<<1152, 256>>>(in_proj_w, x_proj_w, out_proj_w, fc1_w, fc2_w);

    // 1. LN1 -> in_proj GEMM, split x_(bf16) / silu(z)(bf16)
    ln_norm<<<BL, 128>>>(input, pxn1b, ln1_w, ln1_b);
    gemm_bf<1><<<dim3(4, 128), 256, GEMM_SMEM>>>(
        pxn1b, pwin, nullptr, BL, 512, 128, nullptr, nullptr, pszb, px1b,
        nullptr, nullptr);

    // 2. depthwise conv + bias + SiLU (bf16 in/out)
    conv_dw<<<dim3(DI / CPG, HH, BQ), 256, CONV_SMEM>>>(conv_w, conv_b);

    // 3. x_proj: [BL,256]@[256,160]
    gemm_bf<0><<<dim3(2, 128), 256, GEMM_SMEM>>>(
        pxcb, pwxp, pxd, BL, 160, 256, nullptr, nullptr, nullptr, nullptr,
        nullptr, nullptr);

    // 4. selective scan (chunked, 3-pass) + merge
    scan_pass1<<<dim3(16, NCH), 256>>>(dt_w, dt_b, A_log);
    scan_pass2<<<256, 256>>>();
    scan_pass3<<<dim3(16, NCH), 256>>>(dt_w, dt_b, A_log, Ds);

    // 5. out-norm * silu(z) -> bf16; out_proj + residual + fused LN2
    onorm_mul<<<BL, 256>>>(onorm_w, onorm_b);
    gemm_bf<4><<<dim3(1, 128), 256, GEMM_SMEM>>>(
        pynb, pwop, pxmid, BL, 128, 256, nullptr, input, pxn2b, nullptr,
        ln2_w, ln2_b);

    // 6. MLP: fc1+GELU(bf16) -> fc2 + residual
    gemm_bf<2><<<dim3(4, 128), 256, GEMM_SMEM>>>(
        pxn2b, pwf1, nullptr, BL, 512, 128, fc1_b, nullptr, phb, nullptr,
        nullptr, nullptr);
    gemm_bf<3><<<dim3(1, 128), 256, GEMM_SMEM>>>(
        phb, pwf2, (float*)d_out, BL, 128, 512, fc2_b, pxmid, nullptr, nullptr,
        nullptr, nullptr);
}

// round 17
// speedup vs baseline: 1.0069x; 1.0069x over previous
#include <cuda_runtime.h>
#include <cuda_bf16.h>
#include <math.h>
#include <stdint.h>

// Problem constants
#define BQ 4
#define HH 64
#define WW 64
#define CC 128
#define DI 256
#define NS 16
#define RR 8
#define LL 4096       // H*W
#define BL (BQ*LL)    // 16384 pixel-rows
#define CS 128        // scan chunk size
#define NCH (LL/CS)   // 32 chunks

// -------------------- device scratch (static, no allocs) --------------------
__device__ __align__(16) float g_y [BL*DI];        // scan merged output
__device__ __align__(16) float g_xmid[BL*CC];      // after out_proj + residual
__device__ __align__(16) float g_P[16*NCH*NS*DI];
__device__ __align__(16) float g_S[16*NCH*NS*DI];
// bf16 activations
__device__ __align__(16) __nv_bfloat16 g_xdb [BL*160];  // x_proj output
__device__ __align__(16) __nv_bfloat16 g_x1b [BL*DI];   // x_ (conv input)
__device__ __align__(16) __nv_bfloat16 g_szb [BL*DI];   // silu(z)
__device__ __align__(16) __nv_bfloat16 g_xn1b[BL*CC];   // LN1(input)
__device__ __align__(16) __nv_bfloat16 g_xcb [BL*DI];   // conv out (GEMM A + scan xt)
__device__ __align__(16) __nv_bfloat16 g_ynb [BL*DI];   // onorm*silu(z)
__device__ __align__(16) __nv_bfloat16 g_xn2b[BL*CC];   // LN2(xmid)
__device__ __align__(16) __nv_bfloat16 g_hb  [BL*4*CC]; // MLP hidden
// bf16 weights, transposed to [N][K]
__device__ __align__(16) __nv_bfloat16 wb_in[512*128];
__device__ __align__(16) __nv_bfloat16 wb_xp[256*256];
__device__ __align__(16) __nv_bfloat16 wb_op[128*256];
__device__ __align__(16) __nv_bfloat16 wb_f1[512*128];
__device__ __align__(16) __nv_bfloat16 wb_f2[128*512];

// -------------------- small math helpers --------------------
__device__ __forceinline__ float silu_f(float x){ return x / (1.f + __expf(-x)); }
__device__ __forceinline__ float softplus_f(float x){
    return fmaxf(x, 0.f) + __logf(1.f + __expf(-fabsf(x)));
}
__device__ __forceinline__ float gelu_f(float x){
    return 0.5f * x * (1.f + erff(x * 0.70710678118654752f));
}
__device__ __forceinline__ void mma_bf16(float c[4], const uint32_t a[4], const uint32_t b[2]){
    asm volatile(
        "mma.sync.aligned.m16n8k16.row.col.f32.bf16.bf16.f32 "
        "{%0,%1,%2,%3},{%4,%5,%6,%7},{%8,%9},{%0,%1,%2,%3};"
        : "+f"(c[0]), "+f"(c[1]), "+f"(c[2]), "+f"(c[3])
        : "r"(a[0]), "r"(a[1]), "r"(a[2]), "r"(a[3]), "r"(b[0]), "r"(b[1]));
}
__device__ __forceinline__ void cp16(uint32_t dst, const void* src){
    asm volatile("cp.async.cg.shared.global [%0], [%1], 16;" :: "r"(dst), "l"(src));
}
// packed f32x2
__device__ __forceinline__ uint64_t pk2(float lo, float hi){
    uint64_t r; asm("mov.b64 %0, {%1,%2};" : "=l"(r) : "f"(lo), "f"(hi)); return r;
}
__device__ __forceinline__ void upk2(float& lo, float& hi, uint64_t v){
    asm("mov.b64 {%0,%1}, %2;" : "=f"(lo), "=f"(hi) : "l"(v));
}
__device__ __forceinline__ uint64_t mul2(uint64_t a, uint64_t b){
    uint64_t r; asm("mul.rn.f32x2 %0,%1,%2;" : "=l"(r) : "l"(a), "l"(b)); return r;
}
__device__ __forceinline__ uint64_t fma2(uint64_t a, uint64_t b, uint64_t c){
    uint64_t r; asm("fma.rn.f32x2 %0,%1,%2,%3;" : "=l"(r) : "l"(a), "l"(b), "l"(c)); return r;
}
__device__ __forceinline__ int pmap(int k, int T){
    int t = (k & 2) ? (LL - 1 - T) : T;
    return (k & 1) ? ((t & 63) * 64 + (t >> 6)) : t;
}
// convert uint4 of 8 bf16 into two float4
__device__ __forceinline__ void bf8_to_f8(uint4 v, float4& lo, float4& hi){
    __nv_bfloat162* pv = reinterpret_cast<__nv_bfloat162*>(&v);
    float2 f0 = __bfloat1622float2(pv[0]);
    float2 f1 = __bfloat1622float2(pv[1]);
    float2 f2 = __bfloat1622float2(pv[2]);
    float2 f3 = __bfloat1622float2(pv[3]);
    lo = make_float4(f0.x, f0.y, f1.x, f1.y);
    hi = make_float4(f2.x, f2.y, f3.x, f3.y);
}

// -------------------- prep: bf16-convert + transpose all weights --------------------
__global__ void prep(const float* __restrict__ w_in, const float* __restrict__ w_xp,
                     const float* __restrict__ w_op, const float* __restrict__ w_f1,
                     const float* __restrict__ w_f2){
    int idx = blockIdx.x * 256 + threadIdx.x;
    if (idx < 65536){
        int n = idx >> 7, k2 = idx & 127;
        wb_in[idx] = __float2bfloat16(w_in[k2 * 512 + n]);
    } else if (idx < 131072){
        int j = idx - 65536; int n = j >> 8, k2 = j & 255;
        wb_xp[j] = __float2bfloat16((n < 160) ? w_xp[n * 256 + k2] : 0.f);
    } else if (idx < 163840){
        int j = idx - 131072; int n = j >> 8, k2 = j & 255;
        wb_op[j] = __float2bfloat16(w_op[k2 * 128 + n]);
    } else if (idx < 229376){
        int j = idx - 163840; int n = j >> 7, k2 = j & 127;
        wb_f1[j] = __float2bfloat16(w_f1[k2 * 512 + n]);
    } else if (idx < 294912){
        int j = idx - 229376; int n = j >> 9, k2 = j & 511;
        wb_f2[j] = __float2bfloat16(w_f2[k2 * 128 + n]);
    }
}

// -------------------- LN1 (writes bf16 rows) --------------------
__global__ void ln_norm(const float* __restrict__ x, __nv_bfloat16* __restrict__ xo,
                        const float* __restrict__ w, const float* __restrict__ b){
    int row = blockIdx.x;
    float v = x[(size_t)row * CC + threadIdx.x];
    float s1 = v, s2 = v * v;
    #pragma unroll
    for (int o = 16; o; o >>= 1){
        s1 += __shfl_xor_sync(0xffffffffu, s1, o);
        s2 += __shfl_xor_sync(0xffffffffu, s2, o);
    }
    __shared__ float r1[4], r2[4];
    int wi = threadIdx.x >> 5;
    if ((threadIdx.x & 31) == 0){ r1[wi] = s1; r2[wi] = s2; }
    __syncthreads();
    float a = 0.f, bb = 0.f;
    #pragma unroll
    for (int i = 0; i < 4; i++){ a += r1[i]; bb += r2[i]; }
    float mu = a / CC;
    float var = bb / CC - mu * mu;
    float rs = rsqrtf(var + 1e-5f);
    xo[(size_t)row * CC + threadIdx.x] =
        __float2bfloat16((v - mu) * rs * w[threadIdx.x] + b[threadIdx.x]);
}

// -------------------- BF16 tensor-core GEMM, cp.async 3-stage --------------------
#define STG_W 5120
#define A_STGB (128*80)
#define STGB (2*A_STGB)
#define GEMM_SMEM 67584

// EPI: 0 bf16 store (+Nguard) | 1 dual-split bf16 (outb2 = x_, outb = silu(z))
//      2 bias+gelu->bf16 | 3 bias?+residual->fp32 | 4 residual + fused LN
template<int EPI>
__global__ void __launch_bounds__(256, 2) gemm_bf(
    const __nv_bfloat16* __restrict__ A, const __nv_bfloat16* __restrict__ Bw,
    float* __restrict__ Cmat, int M, int Nn, int Kk,
    const float* __restrict__ bias, const float* __restrict__ res,
    __nv_bfloat16* __restrict__ outb, __nv_bfloat16* __restrict__ outb2,
    const float* __restrict__ lnw, const float* __restrict__ lnb)
{
    extern __shared__ float smem[];
    uint32_t sbase;
    { void* p = smem; sbase = (uint32_t)__cvta_generic_to_shared(p); }
    uint32_t* Ss = reinterpret_cast<uint32_t*>(smem);

    const int tid = threadIdx.x;
    const int lane = tid & 31, wid = tid >> 5;
    const int wm = wid & 3, wn = wid >> 2;
    const int t = lane & 3, g = lane >> 2;
    const int bm = blockIdx.y * 128;
    const int bn = blockIdx.x * 128;
    const int lrow = tid >> 2, lc = tid & 3;

    float acc[2][8][4];
    #pragma unroll
    for (int i = 0; i < 2; i++)
        #pragma unroll
        for (int j = 0; j < 8; j++)
            #pragma unroll
            for (int e = 0; e < 4; e++) acc[i][j][e] = 0.f;

    const int nk = Kk >> 5;

    auto load_stage = [&](int stage, int kt){
        uint32_t abase = sbase + stage * STGB;
        #pragma unroll
        for (int q = 0; q < 2; q++){
            int row = q * 64 + lrow;
            cp16(abase + row * 80 + lc * 16,
                 &A[(size_t)(bm + row) * Kk + kt + lc * 8]);
        }
        uint32_t bbase = abase + A_STGB;
        #pragma unroll
        for (int q = 0; q < 2; q++){
            int row = q * 64 + lrow;
            cp16(bbase + row * 80 + lc * 16,
                 &Bw[(size_t)(bn + row) * Kk + kt + lc * 8]);
        }
    };

    load_stage(0, 0);
    asm volatile("cp.async.commit_group;");
    if (nk > 1) load_stage(1, 32);
    asm volatile("cp.async.commit_group;");

    int st = 0;
    for (int i = 0; i < nk; i++){
        asm volatile("cp.async.wait_group 1;");
        __syncthreads();

        const uint32_t* Ab = Ss + st * STG_W;
        const uint32_t* Bb = Ab + 2560;
        if (i + 2 < nk){
            int s2 = st + 2; if (s2 >= 3) s2 -= 3;
            load_stage(s2, (i + 2) << 5);
        }
        asm volatile("cp.async.commit_group;");

        #pragma unroll
        for (int ks = 0; ks < 2; ks++){
            int kw = ks * 8 + t;
            uint32_t afr[2][4];
            #pragma unroll
            for (int mt = 0; mt < 2; mt++){
                int mr = wm * 32 + mt * 16 + g;
                afr[mt][0] = Ab[mr * 20 + kw];
                afr[mt][1] = Ab[(mr + 8) * 20 + kw];
                afr[mt][2] = Ab[mr * 20 + kw + 4];
                afr[mt][3] = Ab[(mr + 8) * 20 + kw + 4];
            }
            uint32_t bfr[8][2];
            #pragma unroll
            for (int nt = 0; nt < 8; nt++){
                int nc = wn * 64 + nt * 8 + g;
                bfr[nt][0] = Bb[nc * 20 + kw];
                bfr[nt][1] = Bb[nc * 20 + kw + 4];
            }
            #pragma unroll
            for (int mt = 0; mt < 2; mt++)
                #pragma unroll
                for (int nt = 0; nt < 8; nt++)
                    mma_bf16(acc[mt][nt], afr[mt], bfr[nt]);
        }
        if (++st == 3) st = 0;
    }

    if (EPI == 4){
        __syncthreads();
        float* sred = smem;   // stride 132
        #pragma unroll
        for (int mt = 0; mt < 2; mt++){
            #pragma unroll
            for (int nt = 0; nt < 8; nt++){
                int cl = wn * 64 + nt * 8 + 2 * t;
                #pragma unroll
                for (int h = 0; h < 2; h++){
                    int rl = wm * 32 + mt * 16 + g + h * 8;
                    float2 rv = *reinterpret_cast<const float2*>(
                        &res[(size_t)(bm + rl) * 128 + cl]);
                    sred[rl * 132 + cl]     = acc[mt][nt][h * 2 + 0] + rv.x;
                    sred[rl * 132 + cl + 1] = acc[mt][nt][h * 2 + 1] + rv.y;
                }
            }
        }
        __syncthreads();
        float4 wv = *reinterpret_cast<const float4*>(&lnw[lane * 4]);
        float4 bv = *reinterpret_cast<const float4*>(&lnb[lane * 4]);
        #pragma unroll
        for (int rr = 0; rr < 16; rr++){
            int rl = wid * 16 + rr;
            float4 v = *reinterpret_cast<const float4*>(&sred[rl * 132 + lane * 4]);
            float s1 = v.x + v.y + v.z + v.w;
            float s2 = fmaf(v.x, v.x, fmaf(v.y, v.y, fmaf(v.z, v.z, v.w * v.w)));
            #pragma unroll
            for (int o = 16; o; o >>= 1){
                s1 += __shfl_xor_sync(0xffffffffu, s1, o);
                s2 += __shfl_xor_sync(0xffffffffu, s2, o);
            }
            float mu = s1 * (1.f / 128.f);
            float var = s2 * (1.f / 128.f) - mu * mu;
            float rs = rsqrtf(var + 1e-5f);
            size_t go = (size_t)(bm + rl) * 128 + lane * 4;
            *reinterpret_cast<float4*>(&Cmat[go]) = v;
            __nv_bfloat162* ob = reinterpret_cast<__nv_bfloat162*>(&outb[go]);
            ob[0] = __floats2bfloat162_rn((v.x - mu) * rs * wv.x + bv.x,
                                          (v.y - mu) * rs * wv.y + bv.y);
            ob[1] = __floats2bfloat162_rn((v.z - mu) * rs * wv.z + bv.z,
                                          (v.w - mu) * rs * wv.w + bv.w);
        }
        return;
    }

    #pragma unroll
    for (int mt = 0; mt < 2; mt++){
        #pragma unroll
        for (int nt = 0; nt < 8; nt++){
            int r0 = bm + wm * 32 + mt * 16 + g;
            int c0 = bn + wn * 64 + nt * 8 + 2 * t;
            #pragma unroll
            for (int h = 0; h < 2; h++){
                int r = r0 + h * 8;
                float v0 = acc[mt][nt][h * 2 + 0];
                float v1 = acc[mt][nt][h * 2 + 1];
                if (EPI == 1){
                    if (c0 < 256)
                        *reinterpret_cast<__nv_bfloat162*>(
                            &outb2[(size_t)r * 256 + c0]) =
                            __floats2bfloat162_rn(v0, v1);
                    else
                        *reinterpret_cast<__nv_bfloat162*>(
                            &outb[(size_t)r * 256 + (c0 - 256)]) =
                            __floats2bfloat162_rn(silu_f(v0), silu_f(v1));
                } else if (EPI == 2){
                    v0 = gelu_f(v0 + bias[c0]);
                    v1 = gelu_f(v1 + bias[c0 + 1]);
                    *reinterpret_cast<__nv_bfloat162*>(&outb[(size_t)r * Nn + c0]) =
                        __floats2bfloat162_rn(v0, v1);
                } else if (EPI == 3){
                    if (bias){ v0 += bias[c0]; v1 += bias[c0 + 1]; }
                    float2 rv = *reinterpret_cast<const float2*>(&res[(size_t)r * Nn + c0]);
                    *reinterpret_cast<float2*>(&Cmat[(size_t)r * Nn + c0]) =
                        make_float2(v0 + rv.x, v1 + rv.y);
                } else {
                    if (c0 < Nn)
                        *reinterpret_cast<__nv_bfloat162*>(&outb[(size_t)r * Nn + c0]) =
                            __floats2bfloat162_rn(v0, v1);
                }
            }
        }
    }
}

// -------------------- depthwise 3x3 conv (bf16 in, bf16 out) --------------------
#define CPG 32
#define CONV_SMEM (3*66*CPG*4)
__global__ void __launch_bounds__(256) conv_dw(const float* __restrict__ wc,
                                               const float* __restrict__ bc){
    extern __shared__ float cs[];   // [3][66][CPG]
    const int c0 = blockIdx.x * CPG;
    const int h  = blockIdx.y;
    const int b  = blockIdx.z;
    const int tid = threadIdx.x;

    if (tid < 48){
        int r = tid / 16;
        int col = (tid >> 3) & 1;
        int c4 = tid & 7;
        *reinterpret_cast<float4*>(&cs[(r * 66 + col * 65) * CPG + c4 * 4]) =
            make_float4(0.f, 0.f, 0.f, 0.f);
    }
    #pragma unroll
    for (int r = 0; r < 3; r++){
        int hh = h + r - 1;
        if (hh >= 0 && hh < HH){
            const __nv_bfloat16* src = &g_x1b[((size_t)(b * LL + hh * WW)) * DI + c0];
            #pragma unroll
            for (int q = 0; q < 2; q++){
                int idx = q * 256 + tid;
                int w = idx >> 3, c4 = idx & 7;
                const __nv_bfloat162* sp = reinterpret_cast<const __nv_bfloat162*>(
                    &src[(size_t)w * DI + c4 * 4]);
                float2 lo = __bfloat1622float2(sp[0]);
                float2 hi = __bfloat1622float2(sp[1]);
                *reinterpret_cast<float4*>(&cs[(r * 66 + w + 1) * CPG + c4 * 4]) =
                    make_float4(lo.x, lo.y, hi.x, hi.y);
            }
        } else {
            #pragma unroll
            for (int q = 0; q < 2; q++){
                int idx = q * 256 + tid;
                int w = idx >> 3, c4 = idx & 7;
                *reinterpret_cast<float4*>(&cs[(r * 66 + w + 1) * CPG + c4 * 4]) =
                    make_float4(0.f, 0.f, 0.f, 0.f);
            }
        }
    }
    __syncthreads();

    const int cg = tid & 15;
    const int wt = tid >> 4;
    const int d = c0 + cg * 2;
    const int w0 = wt * 4;

    float wr[2][9];
    #pragma unroll
    for (int e = 0; e < 2; e++)
        #pragma unroll
        for (int j = 0; j < 9; j++) wr[e][j] = wc[(d + e) * 9 + j];
    const float2 bias = *reinterpret_cast<const float2*>(&bc[d]);

    float2 acc[4];
    #pragma unroll
    for (int o = 0; o < 4; o++) acc[o] = bias;

    #pragma unroll
    for (int r = 0; r < 3; r++){
        #pragma unroll
        for (int j = 0; j < 6; j++){
            float2 v = *reinterpret_cast<const float2*>(
                &cs[(r * 66 + w0 + j) * CPG + cg * 2]);
            #pragma unroll
            for (int o = 0; o < 4; o++){
                if (o <= j && j <= o + 2){
                    int tap = r * 3 + (j - o);
                    acc[o].x = fmaf(wr[0][tap], v.x, acc[o].x);
                    acc[o].y = fmaf(wr[1][tap], v.y, acc[o].y);
                }
            }
        }
    }
    #pragma unroll
    for (int o = 0; o < 4; o++){
        size_t gi = ((size_t)(b * LL + h * WW + w0 + o)) * DI + d;
        *reinterpret_cast<__nv_bfloat162*>(&g_xcb[gi]) =
            __floats2bfloat162_rn(silu_f(acc[o].x), silu_f(acc[o].y));
    }
}

// -------------------- selective scan: pass 1 (chunk-local, dts+B only) --------------------
__global__ void __launch_bounds__(256) scan_pass1(
    const float* __restrict__ dtw, const float* __restrict__ dtb,
    const float* __restrict__ alog)
{
    int bk = blockIdx.x;
    int chunk = blockIdx.y;
    int b = bk >> 2, k = bk & 3;
    int d = threadIdx.x;
    __shared__ __align__(16) float tile[CS * 24];   // dts(8) + B(16)
    int T0 = chunk * CS;
    {
        float4* tile4 = reinterpret_cast<float4*>(tile);
        const uint4* xd4 = reinterpret_cast<const uint4*>(g_xdb);   // 8 bf16 each
        for (int i = d; i < CS * 3; i += 256){
            int t = i / 3, c = i - t * 3;
            int p = pmap(k, T0 + t);
            uint4 v = xd4[(size_t)(b * LL + p) * 20 + k * 5 + c];
            float4 lo, hi;
            bf8_to_f8(v, lo, hi);
            tile4[t * 6 + c * 2]     = lo;
            tile4[t * 6 + c * 2 + 1] = hi;
        }
    }
    __syncthreads();

    float dw[RR];
    #pragma unroll
    for (int r = 0; r < RR; r++) dw[r] = dtw[(size_t)(k * DI + d) * RR + r];
    float db = dtb[k * DI + d];
    float Av[NS];
    #pragma unroll
    for (int n = 0; n < NS; n++) Av[n] = -__expf(alog[(size_t)(k * DI + d) * NS + n]);
    float A0 = Av[0];
    bool fast = true;
    #pragma unroll
    for (int n = 0; n < NS; n++){
        float e = Av[n] - (float)(n + 1) * A0;
        if (fabsf(e) > 1e-5f * fabsf(Av[n]) + 1e-12f) fast = false;
    }
    float dsum = 0.f;
    size_t base = ((size_t)(bk * NCH + chunk) * NS) * DI + d;

    if (fast){
        uint64_t hv[8];
        #pragma unroll
        for (int i = 0; i < 8; i++) hv[i] = pk2(0.f, 0.f);
        for (int t = 0; t < CS; t++){
            int p = pmap(k, T0 + t);
            float xt = __bfloat162float(g_xcb[(size_t)(b * LL + p) * DI + d]);
            const float* tr = &tile[t * 24];
            float4 q0 = *reinterpret_cast<const float4*>(&tr[0]);
            float4 q1 = *reinterpret_cast<const float4*>(&tr[4]);
            float dp = db;
            dp = fmaf(dw[0], q0.x, dp); dp = fmaf(dw[1], q0.y, dp);
            dp = fmaf(dw[2], q0.z, dp); dp = fmaf(dw[3], q0.w, dp);
            dp = fmaf(dw[4], q1.x, dp); dp = fmaf(dw[5], q1.y, dp);
            dp = fmaf(dw[6], q1.z, dp); dp = fmaf(dw[7], q1.w, dp);
            float delta = softplus_f(dp);
            dsum += delta;
            float du = delta * xt;
            float gg = __expf(delta * A0);
            float g2 = gg * gg;
            uint64_t g2v = pk2(g2, g2);
            uint64_t a = pk2(gg, g2);
            uint64_t duv = pk2(du, du);
            #pragma unroll
            for (int j = 0; j < 4; j++){
                ulonglong2 B2 = *reinterpret_cast<const ulonglong2*>(&tr[8 + 4 * j]);
                hv[2*j]   = fma2(a, hv[2*j],   mul2(duv, B2.x));
                a = mul2(a, g2v);
                hv[2*j+1] = fma2(a, hv[2*j+1], mul2(duv, B2.y));
                if (j < 3) a = mul2(a, g2v);
            }
        }
        #pragma unroll
        for (int i = 0; i < 8; i++){
            float lo, hi;
            upk2(lo, hi, hv[i]);
            g_S[base + (size_t)(2 * i) * DI] = lo;
            g_S[base + (size_t)(2 * i + 1) * DI] = hi;
        }
    } else {
        float S[NS];
        #pragma unroll
        for (int n = 0; n < NS; n++) S[n] = 0.f;
        for (int t = 0; t < CS; t++){
            int p = pmap(k, T0 + t);
            float xt = __bfloat162float(g_xcb[(size_t)(b * LL + p) * DI + d]);
            const float* tr = &tile[t * 24];
            float dp = db;
            #pragma unroll
            for (int r = 0; r < RR; r++) dp = fmaf(dw[r], tr[r], dp);
            float delta = softplus_f(dp);
            dsum += delta;
            float du = delta * xt;
            #pragma unroll
            for (int n = 0; n < NS; n++){
                float a = __expf(delta * Av[n]);
                S[n] = fmaf(a, S[n], du * tr[8 + n]);
            }
        }
        #pragma unroll
        for (int n = 0; n < NS; n++) g_S[base + (size_t)n * DI] = S[n];
    }
    #pragma unroll
    for (int n = 0; n < NS; n++)
        g_P[base + (size_t)n * DI] = __expf(dsum * Av[n]);
}

// -------------------- scan pass 2: carry across chunks (+ zero g_y) --------------------
__global__ void scan_pass2(){
    int id = blockIdx.x * 256 + threadIdx.x;
    float4* y4 = reinterpret_cast<float4*>(g_y);
    #pragma unroll
    for (int q = 0; q < 16; q++)
        y4[(size_t)q * 65536 + id] = make_float4(0.f, 0.f, 0.f, 0.f);

    int d  = id & 255;
    int n  = (id >> 8) & 15;
    int bk = id >> 12;
    size_t stride = (size_t)NS * DI;
    size_t base = ((size_t)bk * NCH * NS + n) * DI + d;

    float Pv[NCH], Sv[NCH];
    #pragma unroll
    for (int c = 0; c < NCH; c++){
        Pv[c] = g_P[base + (size_t)c * stride];
        Sv[c] = g_S[base + (size_t)c * stride];
    }
    float Hc = 0.f;
    #pragma unroll
    for (int c = 0; c < NCH; c++){
        g_S[base + (size_t)c * stride] = Hc;
        Hc = fmaf(Pv[c], Hc, Sv[c]);
    }
}

// -------------------- scan pass 3: replay + y + merge (atomic) --------------------
__global__ void __launch_bounds__(256) scan_pass3(
    const float* __restrict__ dtw, const float* __restrict__ dtb,
    const float* __restrict__ alog, const float* __restrict__ Dsv)
{
    int bk = blockIdx.x;
    int chunk = blockIdx.y;
    int b = bk >> 2, k = bk & 3;
    int d = threadIdx.x;
    __shared__ __align__(16) float tile[CS * 40];
    int T0 = chunk * CS;
    {
        float4* tile4 = reinterpret_cast<float4*>(tile);
        const uint4* xd4 = reinterpret_cast<const uint4*>(g_xdb);
        for (int i = d; i < CS * 5; i += 256){
            int t = i / 5, c = i - t * 5;
            int p = pmap(k, T0 + t);
            uint4 v = xd4[(size_t)(b * LL + p) * 20 + k * 5 + c];
            float4 lo, hi;
            bf8_to_f8(v, lo, hi);
            tile4[t * 10 + c * 2]     = lo;
            tile4[t * 10 + c * 2 + 1] = hi;
        }
    }
    __syncthreads();

    float dw[RR];
    #pragma unroll
    for (int r = 0; r < RR; r++) dw[r] = dtw[(size_t)(k * DI + d) * RR + r];
    float db = dtb[k * DI + d];
    float Dk = Dsv[k * DI + d];
    float Av[NS];
    #pragma unroll
    for (int n = 0; n < NS; n++) Av[n] = -__expf(alog[(size_t)(k * DI + d) * NS + n]);
    float A0 = Av[0];
    bool fast = true;
    #pragma unroll
    for (int n = 0; n < NS; n++){
        float e = Av[n] - (float)(n + 1) * A0;
        if (fabsf(e) > 1e-5f * fabsf(Av[n]) + 1e-12f) fast = false;
    }
    size_t base = ((size_t)(bk * NCH + chunk) * NS) * DI + d;

    if (fast){
        uint64_t hv[8];
        #pragma unroll
        for (int i = 0; i < 8; i++)
            hv[i] = pk2(g_S[base + (size_t)(2 * i) * DI],
                        g_S[base + (size_t)(2 * i + 1) * DI]);
        for (int t = 0; t < CS; t++){
            int p = pmap(k, T0 + t);
            size_t pidx = (size_t)(b * LL + p) * DI + d;
            float xt = __bfloat162float(g_xcb[pidx]);
            const float* tr = &tile[t * 40];
            float4 q0 = *reinterpret_cast<const float4*>(&tr[0]);
            float4 q1 = *reinterpret_cast<const float4*>(&tr[4]);
            float dp = db;
            dp = fmaf(dw[0], q0.x, dp); dp = fmaf(dw[1], q0.y, dp);
            dp = fmaf(dw[2], q0.z, dp); dp = fmaf(dw[3], q0.w, dp);
            dp = fmaf(dw[4], q1.x, dp); dp = fmaf(dw[5], q1.y, dp);
            dp = fmaf(dw[6], q1.z, dp); dp = fmaf(dw[7], q1.w, dp);
            float delta = softplus_f(dp);
            float du = delta * xt;
            float gg = __expf(delta * A0);
            float g2 = gg * gg;
            uint64_t g2v = pk2(g2, g2);
            uint64_t a = pk2(gg, g2);
            uint64_t duv = pk2(du, du);
            uint64_t yv = pk2(0.f, 0.f);
            #pragma unroll
            for (int j = 0; j < 4; j++){
                ulonglong2 B2 = *reinterpret_cast<const ulonglong2*>(&tr[8 + 4 * j]);
                ulonglong2 C2 = *reinterpret_cast<const ulonglong2*>(&tr[24 + 4 * j]);
                hv[2*j] = fma2(a, hv[2*j], mul2(duv, B2.x));
                yv = fma2(hv[2*j], C2.x, yv);
                a = mul2(a, g2v);
                hv[2*j+1] = fma2(a, hv[2*j+1], mul2(duv, B2.y));
                yv = fma2(hv[2*j+1], C2.y, yv);
                if (j < 3) a = mul2(a, g2v);
            }
            float ylo, yhi;
            upk2(ylo, yhi, yv);
            float y = ylo + yhi;
            y = fmaf(Dk, xt, y);
            atomicAdd(&g_y[pidx], y);
        }
    } else {
        float h[NS];
        #pragma unroll
        for (int n = 0; n < NS; n++) h[n] = g_S[base + (size_t)n * DI];
        for (int t = 0; t < CS; t++){
            int p = pmap(k, T0 + t);
            size_t pidx = (size_t)(b * LL + p) * DI + d;
            float xt = __bfloat162float(g_xcb[pidx]);
            const float* tr = &tile[t * 40];
            float dp = db;
            #pragma unroll
            for (int r = 0; r < RR; r++) dp = fmaf(dw[r], tr[r], dp);
            float delta = softplus_f(dp);
            float du = delta * xt;
            float y = 0.f;
            #pragma unroll
            for (int n = 0; n < NS; n++){
                float a = __expf(delta * Av[n]);
                h[n] = fmaf(a, h[n], du * tr[8 + n]);
                y = fmaf(h[n], tr[24 + n], y);
            }
            y = fmaf(Dk, xt, y);
            atomicAdd(&g_y[pidx], y);
        }
    }
}

// -------------------- out-norm (LN over DI) * silu(z) -> bf16 --------------------
__global__ void onorm_mul(const float* __restrict__ onw, const float* __restrict__ onb){
    int row = blockIdx.x;
    int d = threadIdx.x;
    float v = g_y[(size_t)row * DI + d];
    float s1 = v, s2 = v * v;
    #pragma unroll
    for (int o = 16; o; o >>= 1){
        s1 += __shfl_xor_sync(0xffffffffu, s1, o);
        s2 += __shfl_xor_sync(0xffffffffu, s2, o);
    }
    __shared__ float r1[8], r2[8];
    int w = d >> 5;
    if ((d & 31) == 0){ r1[w] = s1; r2[w] = s2; }
    __syncthreads();
    float a = 0.f, bsum = 0.f;
    #pragma unroll
    for (int i = 0; i < 8; i++){ a += r1[i]; bsum += r2[i]; }
    float mu = a / DI;
    float var = bsum / DI - mu * mu;
    float rs = rsqrtf(var + 1e-5f);
    float o = (v - mu) * rs * onw[d] + onb[d];
    float sz = __bfloat162float(g_szb[(size_t)row * DI + d]);
    g_ynb[(size_t)row * DI + d] = __float2bfloat16(o * sz);
}

// -------------------- host launch --------------------
extern "C" void kernel_launch(void* const* d_in, const int* in_sizes, int n_in,
                              void* d_out, int out_size)
{
    (void)in_sizes; (void)n_in; (void)out_size;
    const float* input     = (const float*)d_in[0];
    const float* ln1_w     = (const float*)d_in[1];
    const float* ln1_b     = (const float*)d_in[2];
    const float* in_proj_w = (const float*)d_in[3];
    const float* conv_w    = (const float*)d_in[4];
    const float* conv_b    = (const float*)d_in[5];
    const float* x_proj_w  = (const float*)d_in[6];
    const float* dt_w      = (const float*)d_in[7];
    const float* dt_b      = (const float*)d_in[8];
    const float* A_log     = (const float*)d_in[9];
    const float* Ds        = (const float*)d_in[10];
    const float* onorm_w   = (const float*)d_in[11];
    const float* onorm_b   = (const float*)d_in[12];
    const float* out_proj_w= (const float*)d_in[13];
    const float* ln2_w     = (const float*)d_in[14];
    const float* ln2_b     = (const float*)d_in[15];
    const float* fc1_w     = (const float*)d_in[16];
    const float* fc1_b     = (const float*)d_in[17];
    const float* fc2_w     = (const float*)d_in[18];
    const float* fc2_b     = (const float*)d_in[19];

    float *pxmid;
    __nv_bfloat16 *pxdb, *px1b, *pszb, *pxn1b, *pxcb, *pynb, *pxn2b, *phb;
    __nv_bfloat16 *pwin, *pwxp, *pwop, *pwf1, *pwf2;
    cudaGetSymbolAddress((void**)&pxmid,g_xmid);
    cudaGetSymbolAddress((void**)&pxdb, g_xdb);
    cudaGetSymbolAddress((void**)&px1b, g_x1b);
    cudaGetSymbolAddress((void**)&pszb, g_szb);
    cudaGetSymbolAddress((void**)&pxn1b,g_xn1b);
    cudaGetSymbolAddress((void**)&pxcb, g_xcb);
    cudaGetSymbolAddress((void**)&pynb, g_ynb);
    cudaGetSymbolAddress((void**)&pxn2b,g_xn2b);
    cudaGetSymbolAddress((void**)&phb,  g_hb);
    cudaGetSymbolAddress((void**)&pwin, wb_in);
    cudaGetSymbolAddress((void**)&pwxp, wb_xp);
    cudaGetSymbolAddress((void**)&pwop, wb_op);
    cudaGetSymbolAddress((void**)&pwf1, wb_f1);
    cudaGetSymbolAddress((void**)&pwf2, wb_f2);

    static bool attr_done = false;
    if (!attr_done){
        cudaFuncSetAttribute(gemm_bf<0>, cudaFuncAttributeMaxDynamicSharedMemorySize, GEMM_SMEM);
        cudaFuncSetAttribute(gemm_bf<1>, cudaFuncAttributeMaxDynamicSharedMemorySize, GEMM_SMEM);
        cudaFuncSetAttribute(gemm_bf<2>, cudaFuncAttributeMaxDynamicSharedMemorySize, GEMM_SMEM);
        cudaFuncSetAttribute(gemm_bf<3>, cudaFuncAttributeMaxDynamicSharedMemorySize, GEMM_SMEM);
        cudaFuncSetAttribute(gemm_bf<4>, cudaFuncAttributeMaxDynamicSharedMemorySize, GEMM_SMEM);
        cudaFuncSetAttribute(conv_dw,   cudaFuncAttributeMaxDynamicSharedMemorySize, CONV_SMEM);
        attr_done = true;
    }

    // 0. weight conversion (bf16 + transpose)
    prep<<<1152, 256>>>(in_proj_w, x_proj_w, out_proj_w, fc1_w, fc2_w);

    // 1. LN1 -> in_proj GEMM, split x_(bf16) / silu(z)(bf16)
    ln_norm<<<BL, 128>>>(input, pxn1b, ln1_w, ln1_b);
    gemm_bf<1><<<dim3(4, 128), 256, GEMM_SMEM>>>(
        pxn1b, pwin, nullptr, BL, 512, 128, nullptr, nullptr, pszb, px1b,
        nullptr, nullptr);

    // 2. depthwise conv + bias + SiLU (bf16 in/out)
    conv_dw<<<dim3(DI / CPG, HH, BQ), 256, CONV_SMEM>>>(conv_w, conv_b);

    // 3. x_proj: [BL,256]@[256,160] -> bf16
    gemm_bf<0><<<dim3(2, 128), 256, GEMM_SMEM>>>(
        pxcb, pwxp, nullptr, BL, 160, 256, nullptr, nullptr, pxdb, nullptr,
        nullptr, nullptr);

    // 4. selective scan (chunked, 3-pass) + merge
    scan_pass1<<<dim3(16, NCH), 256>>>(dt_w, dt_b, A_log);
    scan_pass2<<<256, 256>>>();
    scan_pass3<<<dim3(16, NCH), 256>>>(dt_w, dt_b, A_log, Ds);

    // 5. out-norm * silu(z) -> bf16; out_proj + residual + fused LN2
    onorm_mul<<<BL, 256>>>(onorm_w, onorm_b);
    gemm_bf<4><<<dim3(1, 128), 256, GEMM_SMEM>>>(
        pynb, pwop, pxmid, BL, 128, 256, nullptr, input, pxn2b, nullptr,
        ln2_w, ln2_b);

    // 6. MLP: fc1+GELU(bf16) -> fc2 + residual
    gemm_bf<2><<<dim3(4, 128), 256, GEMM_SMEM>>>(
        pxn2b, pwf1, nullptr, BL, 512, 128, fc1_b, nullptr, phb, nullptr,
        nullptr, nullptr);
    gemm_bf<3><<<dim3(1, 128), 256, GEMM_SMEM>>>(
        phb, pwf2, (float*)d_out, BL, 128, 512, fc2_b, pxmid, nullptr, nullptr,
        nullptr, nullptr);
}